// round 4
// baseline (speedup 1.0000x reference)
#include <cuda_runtime.h>
#include <stdint.h>

#define NUM_POSES 200

// Precomputed pose matrices: 16 floats per pose (4 rows of float4,
// row 3 = [0,0,0,1] so the apply kernel is branchless).
__device__ float4 g_M[NUM_POSES * 4];

__global__ void build_pose_matrices(const float* __restrict__ R,
                                    const float* __restrict__ T) {
    int p = blockIdx.x * blockDim.x + threadIdx.x;
    if (p >= NUM_POSES) return;

    float wx = R[p * 3 + 0];
    float wy = R[p * 3 + 1];
    float wz = R[p * 3 + 2];

    float theta2 = wx * wx + wy * wy + wz * wz;
    float theta  = sqrtf(theta2 + 1e-12f);
    float a = sinf(theta) / theta;
    float b = (1.0f - cosf(theta)) / fmaxf(theta2, 1e-12f);

    // rot = I + a*K + b*K^2
    float bxy = b * wx * wy;
    float bxz = b * wx * wz;
    float byz = b * wy * wz;

    float tx = T[p * 3 + 0];
    float ty = T[p * 3 + 1];
    float tz = T[p * 3 + 2];

    float4* m = &g_M[p * 4];
    m[0] = make_float4(1.0f - b * (wy * wy + wz * wz),
                       -a * wz + bxy,
                        a * wy + bxz,
                        tx);
    m[1] = make_float4( a * wz + bxy,
                       1.0f - b * (wx * wx + wz * wz),
                       -a * wx + byz,
                        ty);
    m[2] = make_float4(-a * wy + bxz,
                        a * wx + byz,
                       1.0f - b * (wx * wx + wy * wy),
                        tz);
    m[3] = make_float4(0.0f, 0.0f, 0.0f, 1.0f);
}

// One thread per output ROW (float4). 4 threads cooperate on one matrix via
// width-4 shuffles, keeping every global access lane-contiguous (128-bit,
// fully coalesced: 4 L1 wavefronts per warp instruction instead of 16).
__global__ void __launch_bounds__(256)
apply_pose_kernel(const int* __restrict__ n_idx,
                  const float4* __restrict__ E4,   // [N*4] rows of float4
                  float4* __restrict__ out4,       // [N*4] rows of float4
                  int total4) {
    __shared__ float4 sM[NUM_POSES * 4];  // 12.8 KB

    for (int i = threadIdx.x; i < NUM_POSES * 4; i += blockDim.x) {
        sM[i] = g_M[i];
    }
    __syncthreads();

    int i4 = blockIdx.x * blockDim.x + threadIdx.x;
    if (i4 >= total4) return;

    int mat = i4 >> 2;   // matrix index
    int r   = i4 & 3;    // row within matrix

    // Coalesced 128-bit load of this thread's E row.
    float4 e = E4[i4];

    int p = n_idx[mat];
    p = min(max(p, 0), NUM_POSES - 1);

    // Gather all four E rows of this matrix from the 4-lane group.
    const unsigned FULL = 0xffffffffu;
    float4 e0, e1, e2, e3;
    e0.x = __shfl_sync(FULL, e.x, 0, 4);
    e0.y = __shfl_sync(FULL, e.y, 0, 4);
    e0.z = __shfl_sync(FULL, e.z, 0, 4);
    e0.w = __shfl_sync(FULL, e.w, 0, 4);
    e1.x = __shfl_sync(FULL, e.x, 1, 4);
    e1.y = __shfl_sync(FULL, e.y, 1, 4);
    e1.z = __shfl_sync(FULL, e.z, 1, 4);
    e1.w = __shfl_sync(FULL, e.w, 1, 4);
    e2.x = __shfl_sync(FULL, e.x, 2, 4);
    e2.y = __shfl_sync(FULL, e.y, 2, 4);
    e2.z = __shfl_sync(FULL, e.z, 2, 4);
    e2.w = __shfl_sync(FULL, e.w, 2, 4);
    e3.x = __shfl_sync(FULL, e.x, 3, 4);
    e3.y = __shfl_sync(FULL, e.y, 3, 4);
    e3.z = __shfl_sync(FULL, e.z, 3, 4);
    e3.w = __shfl_sync(FULL, e.w, 3, 4);

    // Row coefficients for this output row (row 3 = [0,0,0,1] -> passthrough,
    // handled uniformly: no divergence).
    float4 c = sM[p * 4 + r];

    float4 v;
    v.x = fmaf(c.x, e0.x, fmaf(c.y, e1.x, fmaf(c.z, e2.x, c.w * e3.x)));
    v.y = fmaf(c.x, e0.y, fmaf(c.y, e1.y, fmaf(c.z, e2.y, c.w * e3.y)));
    v.z = fmaf(c.x, e0.z, fmaf(c.y, e1.z, fmaf(c.z, e2.z, c.w * e3.z)));
    v.w = fmaf(c.x, e0.w, fmaf(c.y, e1.w, fmaf(c.z, e2.w, c.w * e3.w)));

    // Coalesced 128-bit store.
    out4[i4] = v;
}

extern "C" void kernel_launch(void* const* d_in, const int* in_sizes, int n_in,
                              void* d_out, int out_size) {
    const int*   n_idx = (const int*)d_in[0];
    const float* E     = (const float*)d_in[1];
    const float* R     = (const float*)d_in[2];
    const float* T     = (const float*)d_in[3];
    float*       out   = (float*)d_out;

    int N = out_size / 16;      // number of 4x4 matrices
    int total4 = N * 4;         // number of float4 rows

    build_pose_matrices<<<1, 256>>>(R, T);

    int threads = 256;
    int blocks = (total4 + threads - 1) / threads;
    apply_pose_kernel<<<blocks, threads>>>(n_idx, (const float4*)E,
                                           (float4*)out, total4);
}